// round 5
// baseline (speedup 1.0000x reference)
#include <cuda_runtime.h>
#include <math.h>

#define BATCH 2
#define TT 16
#define CC 128
#define HW 2304
#define NPIX 2304
#define DI 256
#define DS 16
#define KKEEP 1152
#define NSEQ (BATCH*KKEEP)

// scratch (static device globals; no allocations allowed)
__device__ float g_energy[BATCH*NPIX];
__device__ int   g_idx[BATCH*KKEEP];
__device__ float g_zbuf[(size_t)NSEQ*TT*CC];

// ---------------------------------------------------------------- copy base
__global__ void k_copy(const float4* __restrict__ src, float4* __restrict__ dst, int n4){
    int i = blockIdx.x*blockDim.x + threadIdx.x;
    if (i < n4) dst[i] = src[i];
}

// ---------------------------------------------------------------- energy
__global__ void k_energy(const float* __restrict__ x){
    int id = blockIdx.x*blockDim.x + threadIdx.x;
    if (id >= BATCH*NPIX) return;
    int b = id / NPIX, n = id % NPIX;
    const float* xb = x + (size_t)b*TT*CC*HW + n;
    float e = 0.f;
    for (int t = 0; t < TT; t++){
        const float* xt = xb + (size_t)t*CC*HW;
        float ss = 0.f;
        #pragma unroll 8
        for (int c = 0; c < CC; c++){
            float v = xt[(size_t)c*HW];
            ss += v*v;
        }
        e += sqrtf(ss);
    }
    g_energy[id] = e * (1.f/TT);
}

// ---------------------------------------------------------------- select top-K (stable rank), sorted index output
__global__ void k_select(){
    __shared__ float se[NPIX];
    __shared__ int scnt[768];
    int b = blockIdx.x, tid = threadIdx.x;   // 768 threads, 3 pixels each
    for (int i = tid; i < NPIX; i += 768) se[i] = g_energy[b*NPIX + i];
    __syncthreads();
    int n0 = tid*3;
    float e0 = se[n0], e1 = se[n0+1], e2 = se[n0+2];
    int r0 = 0, r1 = 0, r2 = 0;
    for (int m = 0; m < NPIX; m++){
        float em = se[m];
        r0 += (em > e0) || (em == e0 && m < n0);
        r1 += (em > e1) || (em == e1 && m < n0+1);
        r2 += (em > e2) || (em == e2 && m < n0+2);
    }
    int k0 = r0 < KKEEP, k1 = r1 < KKEEP, k2 = r2 < KKEEP;
    int cnt = k0 + k1 + k2;
    scnt[tid] = cnt;
    __syncthreads();
    for (int off = 1; off < 768; off <<= 1){
        int add = (tid >= off) ? scnt[tid-off] : 0;
        __syncthreads();
        scnt[tid] += add;
        __syncthreads();
    }
    int pos = scnt[tid] - cnt;
    if (k0) g_idx[b*KKEEP + pos++] = n0;
    if (k1) g_idx[b*KKEEP + pos++] = n0+1;
    if (k2) g_idx[b*KKEEP + pos++] = n0+2;
}

// ---------------------------------------------------------------- fused mamba per sequence
// smem floats: sx 2048 | sxi 4096 | szg 4096 | sdt 128 | sB 256 | sC 256 = 10880 (43520 B)
#define SMEM_C_FLOATS 10880
__global__ void __launch_bounds__(256, 3)
k_mamba(const float* __restrict__ x,
        const float* __restrict__ norm1_w,
        const float* __restrict__ in_w,
        const float* __restrict__ conv_w,
        const float* __restrict__ conv_b,
        const float* __restrict__ xp_w,
        const float* __restrict__ dt_w,
        const float* __restrict__ dt_b,
        const float* __restrict__ A_log,
        const float* __restrict__ Dp,
        const float* __restrict__ out_w){
    extern __shared__ float sm[];
    float* sx  = sm;             // [16][128]
    float* sxi = sx + 2048;      // [16][256] xi -> xc
    float* szg = sxi + 4096;     // [16][256] z-gate -> y_act
    float* sdt = szg + 4096;     // [16][8]
    float* sB  = sdt + 128;      // [16][16]
    float* sC  = sB + 256;       // [16][16]

    const int tid = threadIdx.x;
    const int seq = blockIdx.x;
    const int b = seq / KKEEP;
    const int n = g_idx[b*KKEEP + (seq % KKEEP)];

    // gather input rows
    const float* xb = x + (size_t)b*TT*CC*HW + n;
    for (int i = tid; i < TT*CC; i += 256){
        sx[i] = xb[(size_t)i * HW];
    }
    __syncthreads();

    // rmsnorm (norm1)
    const int wid = tid >> 5, lane = tid & 31;
    for (int r = wid; r < TT; r += 8){
        float* row = sx + r*CC;
        float v0 = row[lane], v1 = row[lane+32], v2 = row[lane+64], v3 = row[lane+96];
        float ss = v0*v0 + v1*v1 + v2*v2 + v3*v3;
        ss += __shfl_xor_sync(0xffffffffu, ss, 16);
        ss += __shfl_xor_sync(0xffffffffu, ss, 8);
        ss += __shfl_xor_sync(0xffffffffu, ss, 4);
        ss += __shfl_xor_sync(0xffffffffu, ss, 2);
        ss += __shfl_xor_sync(0xffffffffu, ss, 1);
        float sc = rsqrtf(ss*(1.f/CC) + 1e-5f);
        row[lane]    = v0*sc*norm1_w[lane];
        row[lane+32] = v1*sc*norm1_w[lane+32];
        row[lane+64] = v2*sc*norm1_w[lane+64];
        row[lane+96] = v3*sc*norm1_w[lane+96];
    }
    __syncthreads();

    // in_proj: [16,128] @ [512,128]^T. Thread owns rows tid and tid+256, all 16 t.
    // Weights stream from L1/L2 via LDG (shared across all blocks); acts are smem broadcast.
    {
        #pragma unroll
        for (int half = 0; half < 2; half++){
            const int j = tid + half*DI;
            const float4* wr = (const float4*)(in_w) + j*32;
            float acc[TT];
            #pragma unroll
            for (int t = 0; t < TT; t++) acc[t] = 0.f;
            #pragma unroll 4
            for (int q = 0; q < 32; q++){
                float4 w = __ldg(wr + q);
                #pragma unroll
                for (int t = 0; t < TT; t++){
                    float4 a = ((const float4*)(sx + t*CC))[q];
                    acc[t] += a.x*w.x + a.y*w.y + a.z*w.z + a.w*w.w;
                }
            }
            float* dst = half ? (szg + tid) : (sxi + tid);
            #pragma unroll
            for (int t = 0; t < TT; t++) dst[t*DI] = acc[t];
        }
    }
    // (no sync needed: conv/scan thread d==tid consumes only columns written by itself)

    // causal depthwise conv (k=4) + SiLU, per channel
    {
        const int d = tid;
        const float w0 = conv_w[d*4], w1 = conv_w[d*4+1], w2 = conv_w[d*4+2], w3 = conv_w[d*4+3];
        const float cb = conv_b[d];
        float xv[TT+3];
        xv[0] = xv[1] = xv[2] = 0.f;
        #pragma unroll
        for (int t = 0; t < TT; t++) xv[t+3] = sxi[t*DI + d];
        #pragma unroll
        for (int t = 0; t < TT; t++){
            float a = cb + w0*xv[t] + w1*xv[t+1] + w2*xv[t+2] + w3*xv[t+3];
            sxi[t*DI + d] = a / (1.f + __expf(-a));
        }
    }
    __syncthreads();

    // x_proj: [16,256] @ [40,256]^T. Thread (jl<40, tg of 4 t) streams weight row via LDG.
    {
        const int jl = tid & 63, tg = tid >> 6;
        if (jl < 40){
            const float4* wr = (const float4*)(xp_w) + jl*64;
            const float4* y0 = (const float4*)(sxi + (tg*4+0)*DI);
            const float4* y1 = (const float4*)(sxi + (tg*4+1)*DI);
            const float4* y2 = (const float4*)(sxi + (tg*4+2)*DI);
            const float4* y3 = (const float4*)(sxi + (tg*4+3)*DI);
            float a0 = 0.f, a1 = 0.f, a2 = 0.f, a3 = 0.f;
            #pragma unroll 8
            for (int q = 0; q < 64; q++){
                float4 w = __ldg(wr + q);
                float4 v = y0[q];
                a0 += v.x*w.x + v.y*w.y + v.z*w.z + v.w*w.w;
                v = y1[q];
                a1 += v.x*w.x + v.y*w.y + v.z*w.z + v.w*w.w;
                v = y2[q];
                a2 += v.x*w.x + v.y*w.y + v.z*w.z + v.w*w.w;
                v = y3[q];
                a3 += v.x*w.x + v.y*w.y + v.z*w.z + v.w*w.w;
            }
            #pragma unroll
            for (int u = 0; u < 4; u++){
                int t = tg*4 + u;
                float acc = (u == 0) ? a0 : (u == 1) ? a1 : (u == 2) ? a2 : a3;
                if (jl < 8)       sdt[t*8 + jl] = acc;
                else if (jl < 24) sB[t*16 + (jl-8)] = acc;
                else              sC[t*16 + (jl-24)] = acc;
            }
        }
        __syncthreads();
    }

    // dt_proj + softplus + selective scan + gate (thread d owns channel d)
    {
        const int d = tid;
        float wdt[8];
        #pragma unroll
        for (int r = 0; r < 8; r++) wdt[r] = dt_w[d*8 + r];
        const float bdt = dt_b[d];
        float Ar[DS];
        #pragma unroll
        for (int s = 0; s < DS; s++) Ar[s] = -__expf(A_log[d*DS + s]);
        const float Dd = Dp[d];
        float h[DS];
        #pragma unroll
        for (int s = 0; s < DS; s++) h[s] = 0.f;
        for (int t = 0; t < TT; t++){
            float dtr = bdt;
            #pragma unroll
            for (int r = 0; r < 8; r++) dtr += sdt[t*8 + r]*wdt[r];
            float dtv = (dtr > 20.f) ? dtr : log1pf(__expf(dtr));
            float xcv = sxi[t*DI + d];
            float coef = dtv * xcv;
            float y = 0.f;
            #pragma unroll
            for (int s = 0; s < DS; s++){
                float dA = __expf(dtv * Ar[s]);
                h[s] = dA*h[s] + coef*sB[t*16 + s];
                y += h[s]*sC[t*16 + s];
            }
            float zg = szg[t*DI + d];
            szg[t*DI + d] = (y + xcv*Dd) * (zg / (1.f + __expf(-zg)));
        }
    }
    __syncthreads();

    // out_proj: [16,256] @ [128,256]^T. Thread (c=tid&127, tg=tid>>7) -> 8 t each.
    {
        const int c = tid & 127, tg = tid >> 7;
        const float4* wr = (const float4*)(out_w) + c*64;
        const float* yp = szg + tg*8*DI;
        float acc[8];
        #pragma unroll
        for (int i = 0; i < 8; i++) acc[i] = 0.f;
        #pragma unroll 4
        for (int q = 0; q < 64; q++){
            float4 w = __ldg(wr + q);
            #pragma unroll
            for (int i = 0; i < 8; i++){
                float4 a = ((const float4*)(yp + i*DI))[q];
                acc[i] += a.x*w.x + a.y*w.y + a.z*w.z + a.w*w.w;
            }
        }
        float* zb = g_zbuf + (size_t)seq*TT*CC + c;
        #pragma unroll
        for (int i = 0; i < 8; i++) zb[(tg*8 + i)*CC] = acc[i];
    }
}

// ---------------------------------------------------------------- mix MLP + scatter (2 sequences per block)
// smem floats: sz 4096 | sh1 4096 = 8192 (32768 B)
#define SMEM_D_FLOATS 8192
__global__ void __launch_bounds__(256, 3)
k_mix(const float* __restrict__ x,
      const float* __restrict__ norm2_w,
      const float* __restrict__ w1, const float* __restrict__ b1,
      const float* __restrict__ w2, const float* __restrict__ b2,
      float* __restrict__ out){
    extern __shared__ float sm[];
    float* sz  = sm;            // [2][16][128]
    float* sh1 = sz + 4096;     // [2][16][128]

    const int tid = threadIdx.x;
    const int s0 = blockIdx.x * 2;
    int bb[2], nn[2];
    #pragma unroll
    for (int g = 0; g < 2; g++){
        int s = s0 + g;
        bb[g] = s / KKEEP;
        nn[g] = g_idx[bb[g]*KKEEP + (s % KKEEP)];
    }
    for (int g = 0; g < 2; g++)
        for (int i = tid; i < TT*CC; i += 256)
            sz[g*2048 + i] = g_zbuf[(size_t)(s0+g)*TT*CC + i];
    __syncthreads();

    // rmsnorm (norm2) over 32 rows
    const int wid = tid >> 5, lane = tid & 31;
    for (int r = wid; r < 32; r += 8){
        float* row = sz + r*CC;
        float v0 = row[lane], v1 = row[lane+32], v2 = row[lane+64], v3 = row[lane+96];
        float ss = v0*v0 + v1*v1 + v2*v2 + v3*v3;
        ss += __shfl_xor_sync(0xffffffffu, ss, 16);
        ss += __shfl_xor_sync(0xffffffffu, ss, 8);
        ss += __shfl_xor_sync(0xffffffffu, ss, 4);
        ss += __shfl_xor_sync(0xffffffffu, ss, 2);
        ss += __shfl_xor_sync(0xffffffffu, ss, 1);
        float sc = rsqrtf(ss*(1.f/CC) + 1e-5f);
        row[lane]    = v0*sc*norm2_w[lane];
        row[lane+32] = v1*sc*norm2_w[lane+32];
        row[lane+64] = v2*sc*norm2_w[lane+64];
        row[lane+96] = v3*sc*norm2_w[lane+96];
    }
    __syncthreads();

    const int c = tid & 127, tg = tid >> 7;   // 128 cols x 2 groups of 16 rows

    // w1 GEMM + exact GELU; weights via LDG, acts broadcast from smem
    {
        const float4* wr = (const float4*)(w1) + c*32;
        const float* zp = sz + tg*16*CC;      // 16 of the 32 rows
        float acc[16];
        const float bias = b1[c];
        #pragma unroll
        for (int i = 0; i < 16; i++) acc[i] = bias;
        #pragma unroll 4
        for (int q = 0; q < 32; q++){
            float4 w = __ldg(wr + q);
            #pragma unroll
            for (int i = 0; i < 16; i++){
                float4 a = ((const float4*)(zp + i*CC))[q];
                acc[i] += a.x*w.x + a.y*w.y + a.z*w.z + a.w*w.w;
            }
        }
        float* hp = sh1 + tg*16*CC + c;
        #pragma unroll
        for (int i = 0; i < 16; i++){
            float v = acc[i];
            hp[i*CC] = 0.5f*v*(1.f + erff(v*0.70710678118654752f));
        }
    }
    __syncthreads();

    // w2 GEMM + residual scatter
    {
        const float4* wr = (const float4*)(w2) + c*32;
        const float* hp = sh1 + tg*16*CC;
        float acc[16];
        const float bias = b2[c];
        #pragma unroll
        for (int i = 0; i < 16; i++) acc[i] = bias;
        #pragma unroll 4
        for (int q = 0; q < 32; q++){
            float4 w = __ldg(wr + q);
            #pragma unroll
            for (int i = 0; i < 16; i++){
                float4 a = ((const float4*)(hp + i*CC))[q];
                acc[i] += a.x*w.x + a.y*w.y + a.z*w.z + a.w*w.w;
            }
        }
        // rows tg*16 .. tg*16+15 span: g = (tg*16+i)/16, t = (tg*16+i)%16 -> g==tg here
        const int g = tg;
        const size_t baseb = (size_t)bb[g]*TT*CC*HW + nn[g];
        #pragma unroll
        for (int i = 0; i < 16; i++){
            size_t pos = baseb + (size_t)(i*CC + c)*HW;
            out[pos] = x[pos] + acc[i];
        }
    }
}

// ---------------------------------------------------------------- launch
extern "C" void kernel_launch(void* const* d_in, const int* in_sizes, int n_in,
                              void* d_out, int out_size){
    const float* x    = (const float*)d_in[0];
    const float* n1w  = (const float*)d_in[1];
    const float* n2w  = (const float*)d_in[2];
    const float* inw  = (const float*)d_in[3];
    const float* cw   = (const float*)d_in[4];
    const float* cb   = (const float*)d_in[5];
    const float* xpw  = (const float*)d_in[6];
    const float* dtw  = (const float*)d_in[7];
    const float* dtb  = (const float*)d_in[8];
    const float* alog = (const float*)d_in[9];
    const float* dp   = (const float*)d_in[10];
    const float* ow   = (const float*)d_in[11];
    const float* w1   = (const float*)d_in[12];
    const float* b1   = (const float*)d_in[13];
    const float* w2   = (const float*)d_in[14];
    const float* b2   = (const float*)d_in[15];
    float* out = (float*)d_out;

    cudaFuncSetAttribute(k_mamba, cudaFuncAttributeMaxDynamicSharedMemorySize, SMEM_C_FLOATS*4);
    cudaFuncSetAttribute(k_mix,   cudaFuncAttributeMaxDynamicSharedMemorySize, SMEM_D_FLOATS*4);

    const int n4 = out_size / 4;
    k_copy<<<(n4 + 255)/256, 256>>>((const float4*)x, (float4*)out, n4);
    k_energy<<<(BATCH*NPIX + 255)/256, 256>>>(x);
    k_select<<<BATCH, 768>>>();
    k_mamba<<<NSEQ, 256, SMEM_C_FLOATS*4>>>(x, n1w, inw, cw, cb, xpw, dtw, dtb, alog, dp, ow);
    k_mix<<<NSEQ/2, 256, SMEM_D_FLOATS*4>>>(x, n2w, w1, b1, w2, b2, out);
}

// round 6
// speedup vs baseline: 1.5064x; 1.5064x over previous
#include <cuda_runtime.h>
#include <math.h>

#define BATCH 2
#define TT 16
#define CC 128
#define HW 2304
#define NPIX 2304
#define DI 256
#define DS 16
#define KKEEP 1152
#define NSEQ (BATCH*KKEEP)

// scratch (static device globals; no allocations allowed)
__device__ float g_energy[BATCH*NPIX];
__device__ int   g_idx[BATCH*KKEEP];
__device__ float g_zbuf[(size_t)NSEQ*TT*CC];
// transposed weights [k][j]
__device__ float g_inwT[128*512];
__device__ float g_xpwT[256*64];     // padded 40 -> 64 cols (zeros)
__device__ float g_owT[256*128];
__device__ float g_w1T[128*128];
__device__ float g_w2T[128*128];

// ---------------------------------------------------------------- weight transpose (tiny)
__global__ void k_wt(const float* __restrict__ in_w, const float* __restrict__ xp_w,
                     const float* __restrict__ out_w, const float* __restrict__ w1,
                     const float* __restrict__ w2){
    int id = blockIdx.x*256 + threadIdx.x;
    if (id < 65536){ int k=id>>9, j=id&511; g_inwT[id] = in_w[j*128+k]; return; }
    id -= 65536;
    if (id < 16384){ int k=id>>6, j=id&63; g_xpwT[id] = (j<40) ? xp_w[j*256+k] : 0.f; return; }
    id -= 16384;
    if (id < 32768){ int k=id>>7, j=id&127; g_owT[id] = out_w[j*256+k]; return; }
    id -= 32768;
    if (id < 16384){ int k=id>>7, j=id&127; g_w1T[id] = w1[j*128+k]; return; }
    id -= 16384;
    if (id < 16384){ int k=id>>7, j=id&127; g_w2T[id] = w2[j*128+k]; }
}

// ---------------------------------------------------------------- copy base
__global__ void k_copy(const float4* __restrict__ src, float4* __restrict__ dst, int n4){
    int i = blockIdx.x*blockDim.x + threadIdx.x;
    if (i < n4) dst[i] = src[i];
}

// ---------------------------------------------------------------- energy
__global__ void k_energy(const float* __restrict__ x){
    int id = blockIdx.x*blockDim.x + threadIdx.x;
    if (id >= BATCH*NPIX) return;
    int b = id / NPIX, n = id % NPIX;
    const float* xb = x + (size_t)b*TT*CC*HW + n;
    float e = 0.f;
    for (int t = 0; t < TT; t++){
        const float* xt = xb + (size_t)t*CC*HW;
        float ss = 0.f;
        #pragma unroll 8
        for (int c = 0; c < CC; c++){
            float v = xt[(size_t)c*HW];
            ss += v*v;
        }
        e += sqrtf(ss);
    }
    g_energy[id] = e * (1.f/TT);
}

// ---------------------------------------------------------------- select top-K (stable rank), sorted index output
__global__ void k_select(){
    __shared__ float se[NPIX];
    __shared__ int scnt[768];
    int b = blockIdx.x, tid = threadIdx.x;
    for (int i = tid; i < NPIX; i += 768) se[i] = g_energy[b*NPIX + i];
    __syncthreads();
    int n0 = tid*3;
    float e0 = se[n0], e1 = se[n0+1], e2 = se[n0+2];
    int r0 = 0, r1 = 0, r2 = 0;
    for (int m = 0; m < NPIX; m++){
        float em = se[m];
        r0 += (em > e0) || (em == e0 && m < n0);
        r1 += (em > e1) || (em == e1 && m < n0+1);
        r2 += (em > e2) || (em == e2 && m < n0+2);
    }
    int k0 = r0 < KKEEP, k1 = r1 < KKEEP, k2 = r2 < KKEEP;
    int cnt = k0 + k1 + k2;
    scnt[tid] = cnt;
    __syncthreads();
    for (int off = 1; off < 768; off <<= 1){
        int add = (tid >= off) ? scnt[tid-off] : 0;
        __syncthreads();
        scnt[tid] += add;
        __syncthreads();
    }
    int pos = scnt[tid] - cnt;
    if (k0) g_idx[b*KKEEP + pos++] = n0;
    if (k1) g_idx[b*KKEEP + pos++] = n0+1;
    if (k2) g_idx[b*KKEEP + pos++] = n0+2;
}

// FMA of scalar s against a j-quad w into 4 accumulators
#define QFMA(ACC, I, S, W) \
    ACC[0][I] += (S)*(W).x; ACC[1][I] += (S)*(W).y; ACC[2][I] += (S)*(W).z; ACC[3][I] += (S)*(W).w;

// ---------------------------------------------------------------- fused mamba per sequence
// smem floats: sx 2048 | sxi 4096 | szg 4096 | sdt 128 | sB 256 | sC 256 | red 8192 = 19072 (76288 B)
#define SMEM_C_FLOATS 19072
__global__ void __launch_bounds__(256, 2)
k_mamba(const float* __restrict__ x,
        const float* __restrict__ norm1_w,
        const float* __restrict__ conv_w,
        const float* __restrict__ conv_b,
        const float* __restrict__ dt_w,
        const float* __restrict__ dt_b,
        const float* __restrict__ A_log,
        const float* __restrict__ Dp){
    extern __shared__ float sm[];
    float* sx  = sm;             // [16][128]
    float* sxi = sm + 2048;      // [16][256] xi -> xc
    float* szg = sm + 6144;      // [16][256] z-gate -> y_act
    float* sdt = sm + 10240;     // [16][8]
    float* sB  = sm + 10368;     // [16][16]
    float* sC  = sm + 10624;     // [16][16]
    float* red = sm + 10880;     // [4][2048] k-split partials

    const int tid = threadIdx.x;
    const int seq = blockIdx.x;
    const int b = seq / KKEEP;
    const int n = g_idx[b*KKEEP + (seq % KKEEP)];

    // gather input rows
    const float* xb = x + (size_t)b*TT*CC*HW + n;
    for (int i = tid; i < TT*CC; i += 256){
        sx[i] = xb[(size_t)i * HW];
    }
    __syncthreads();

    // rmsnorm (norm1)
    const int wid = tid >> 5, lane = tid & 31;
    for (int r = wid; r < TT; r += 8){
        float* row = sx + r*CC;
        float v0 = row[lane], v1 = row[lane+32], v2 = row[lane+64], v3 = row[lane+96];
        float ss = v0*v0 + v1*v1 + v2*v2 + v3*v3;
        ss += __shfl_xor_sync(0xffffffffu, ss, 16);
        ss += __shfl_xor_sync(0xffffffffu, ss, 8);
        ss += __shfl_xor_sync(0xffffffffu, ss, 4);
        ss += __shfl_xor_sync(0xffffffffu, ss, 2);
        ss += __shfl_xor_sync(0xffffffffu, ss, 1);
        float sc = rsqrtf(ss*(1.f/CC) + 1e-5f);
        row[lane]    = v0*sc*norm1_w[lane];
        row[lane+32] = v1*sc*norm1_w[lane+32];
        row[lane+64] = v2*sc*norm1_w[lane+64];
        row[lane+96] = v3*sc*norm1_w[lane+96];
    }
    __syncthreads();

    // in_proj: [16,128] @ wT[128][512]. Thread: j-quad (jq=tid&127), 8 t (tg=tid>>7).
    // Coalesced weight LDG (lanes = adjacent quads), broadcast act LDS.
    {
        const int jq = tid & 127, tg = tid >> 7;
        const float4* wT = (const float4*)g_inwT;          // [k][128 quads]
        const float4* ax = (const float4*)(sx + tg*8*CC);  // row i at + i*32
        float acc[4][8];
        #pragma unroll
        for (int j = 0; j < 4; j++)
            #pragma unroll
            for (int i = 0; i < 8; i++) acc[j][i] = 0.f;
        for (int qq = 0; qq < 32; qq++){
            float4 act[8];
            #pragma unroll
            for (int i = 0; i < 8; i++) act[i] = ax[i*32 + qq];
            float4 w;
            w = __ldg(wT + (qq*4+0)*128 + jq);
            #pragma unroll
            for (int i = 0; i < 8; i++){ QFMA(acc, i, act[i].x, w) }
            w = __ldg(wT + (qq*4+1)*128 + jq);
            #pragma unroll
            for (int i = 0; i < 8; i++){ QFMA(acc, i, act[i].y, w) }
            w = __ldg(wT + (qq*4+2)*128 + jq);
            #pragma unroll
            for (int i = 0; i < 8; i++){ QFMA(acc, i, act[i].z, w) }
            w = __ldg(wT + (qq*4+3)*128 + jq);
            #pragma unroll
            for (int i = 0; i < 8; i++){ QFMA(acc, i, act[i].w, w) }
        }
        float* dst = (jq < 64) ? (sxi + 4*jq) : (szg + 4*jq - 256);
        #pragma unroll
        for (int i = 0; i < 8; i++){
            *(float4*)(dst + (tg*8+i)*DI) = make_float4(acc[0][i], acc[1][i], acc[2][i], acc[3][i]);
        }
    }
    __syncthreads();

    // causal depthwise conv (k=4) + SiLU, per channel
    {
        const int d = tid;
        const float w0 = conv_w[d*4], w1 = conv_w[d*4+1], w2 = conv_w[d*4+2], w3 = conv_w[d*4+3];
        const float cb = conv_b[d];
        float xv[TT+3];
        xv[0] = xv[1] = xv[2] = 0.f;
        #pragma unroll
        for (int t = 0; t < TT; t++) xv[t+3] = sxi[t*DI + d];
        #pragma unroll
        for (int t = 0; t < TT; t++){
            float a = cb + w0*xv[t] + w1*xv[t+1] + w2*xv[t+2] + w3*xv[t+3];
            sxi[t*DI + d] = a / (1.f + __expf(-a));
        }
    }
    __syncthreads();

    // x_proj: [16,256] @ wT[256][64pad]. K-split 4 x 64k; thread: j-quad(16), 4 t, kg.
    {
        const int jq = tid & 15;
        const int tg = (tid >> 4) & 3;
        const int kg = tid >> 6;
        const float4* wT = (const float4*)g_xpwT;           // [k][16 quads]
        const float4* ax = (const float4*)(sxi + tg*4*DI);  // row i at + i*64
        float acc[4][4];
        #pragma unroll
        for (int j = 0; j < 4; j++)
            #pragma unroll
            for (int i = 0; i < 4; i++) acc[j][i] = 0.f;
        for (int qq = 0; qq < 16; qq++){
            const int q0 = kg*16 + qq;
            float4 act[4];
            #pragma unroll
            for (int i = 0; i < 4; i++) act[i] = ax[i*64 + q0];
            float4 w;
            w = __ldg(wT + (q0*4+0)*16 + jq);
            #pragma unroll
            for (int i = 0; i < 4; i++){ QFMA(acc, i, act[i].x, w) }
            w = __ldg(wT + (q0*4+1)*16 + jq);
            #pragma unroll
            for (int i = 0; i < 4; i++){ QFMA(acc, i, act[i].y, w) }
            w = __ldg(wT + (q0*4+2)*16 + jq);
            #pragma unroll
            for (int i = 0; i < 4; i++){ QFMA(acc, i, act[i].z, w) }
            w = __ldg(wT + (q0*4+3)*16 + jq);
            #pragma unroll
            for (int i = 0; i < 4; i++){ QFMA(acc, i, act[i].w, w) }
        }
        #pragma unroll
        for (int i = 0; i < 4; i++){
            *(float4*)(red + kg*1024 + (tg*4+i)*64 + 4*jq) =
                make_float4(acc[0][i], acc[1][i], acc[2][i], acc[3][i]);
        }
    }
    __syncthreads();
    // reduce 4 partials -> route to sdt/sB/sC (1024 floats = 256 f4, 1 per thread)
    {
        const float4* r4 = (const float4*)red;
        float4 s0 = r4[tid], s1 = r4[256+tid], s2 = r4[512+tid], s3 = r4[768+tid];
        float v[4] = { s0.x+s1.x+s2.x+s3.x, s0.y+s1.y+s2.y+s3.y,
                       s0.z+s1.z+s2.z+s3.z, s0.w+s1.w+s2.w+s3.w };
        #pragma unroll
        for (int c = 0; c < 4; c++){
            int idx = tid*4 + c;
            int j = idx & 63, t = idx >> 6;
            if (j < 8)       sdt[t*8 + j] = v[c];
            else if (j < 24) sB[t*16 + (j-8)] = v[c];
            else if (j < 40) sC[t*16 + (j-24)] = v[c];
        }
    }
    __syncthreads();

    // dt_proj + softplus + selective scan + gate (thread d owns channel d)
    {
        const int d = tid;
        float wdt[8];
        #pragma unroll
        for (int r = 0; r < 8; r++) wdt[r] = dt_w[d*8 + r];
        const float bdt = dt_b[d];
        float Ar[DS];
        #pragma unroll
        for (int s = 0; s < DS; s++) Ar[s] = -__expf(A_log[d*DS + s]);
        const float Dd = Dp[d];
        float h[DS];
        #pragma unroll
        for (int s = 0; s < DS; s++) h[s] = 0.f;
        for (int t = 0; t < TT; t++){
            float dtr = bdt;
            #pragma unroll
            for (int r = 0; r < 8; r++) dtr += sdt[t*8 + r]*wdt[r];
            float dtv = (dtr > 20.f) ? dtr : log1pf(__expf(dtr));
            float xcv = sxi[t*DI + d];
            float coef = dtv * xcv;
            float y = 0.f;
            #pragma unroll
            for (int s = 0; s < DS; s++){
                float dA = __expf(dtv * Ar[s]);
                h[s] = dA*h[s] + coef*sB[t*16 + s];
                y += h[s]*sC[t*16 + s];
            }
            float zg = szg[t*DI + d];
            szg[t*DI + d] = (y + xcv*Dd) * (zg / (1.f + __expf(-zg)));
        }
    }
    __syncthreads();

    // out_proj: [16,256] @ wT[256][128]. K-split 4 x 64k; thread: j-quad(32), 8 t (tg), kg.
    {
        const int jq = tid & 31;
        const int tg = (tid >> 5) & 1;
        const int kg = tid >> 6;
        const float4* wT = (const float4*)g_owT;            // [k][32 quads]
        const float4* ay = (const float4*)(szg + tg*8*DI);  // row i at + i*64
        float acc[4][8];
        #pragma unroll
        for (int j = 0; j < 4; j++)
            #pragma unroll
            for (int i = 0; i < 8; i++) acc[j][i] = 0.f;
        for (int qq = 0; qq < 16; qq++){
            const int q0 = kg*16 + qq;
            float4 act[8];
            #pragma unroll
            for (int i = 0; i < 8; i++) act[i] = ay[i*64 + q0];
            float4 w;
            w = __ldg(wT + (q0*4+0)*32 + jq);
            #pragma unroll
            for (int i = 0; i < 8; i++){ QFMA(acc, i, act[i].x, w) }
            w = __ldg(wT + (q0*4+1)*32 + jq);
            #pragma unroll
            for (int i = 0; i < 8; i++){ QFMA(acc, i, act[i].y, w) }
            w = __ldg(wT + (q0*4+2)*32 + jq);
            #pragma unroll
            for (int i = 0; i < 8; i++){ QFMA(acc, i, act[i].z, w) }
            w = __ldg(wT + (q0*4+3)*32 + jq);
            #pragma unroll
            for (int i = 0; i < 8; i++){ QFMA(acc, i, act[i].w, w) }
        }
        #pragma unroll
        for (int i = 0; i < 8; i++){
            *(float4*)(red + kg*2048 + (tg*8+i)*128 + 4*jq) =
                make_float4(acc[0][i], acc[1][i], acc[2][i], acc[3][i]);
        }
    }
    __syncthreads();
    // reduce 4 partials, write zbuf (coalesced): 2048 floats = 512 f4, 2 per thread
    {
        const float4* r4 = (const float4*)red;
        float4* zb = (float4*)(g_zbuf + (size_t)seq*TT*CC);
        #pragma unroll
        for (int p = 0; p < 2; p++){
            int o = tid + p*256;
            float4 s0 = r4[o], s1 = r4[512+o], s2 = r4[1024+o], s3 = r4[1536+o];
            zb[o] = make_float4(s0.x+s1.x+s2.x+s3.x, s0.y+s1.y+s2.y+s3.y,
                                s0.z+s1.z+s2.z+s3.z, s0.w+s1.w+s2.w+s3.w);
        }
    }
}

// ---------------------------------------------------------------- mix MLP + scatter (4 sequences per block)
// smem floats: sz 8192 | sh1 8192 = 16384 (65536 B)
#define SMEM_D_FLOATS 16384
__global__ void __launch_bounds__(256, 2)
k_mix(const float* __restrict__ x,
      const float* __restrict__ norm2_w,
      const float* __restrict__ b1, const float* __restrict__ b2,
      float* __restrict__ out){
    extern __shared__ float sm[];
    float* sz  = sm;            // [64][128]
    float* sh1 = sm + 8192;     // [64][128]

    const int tid = threadIdx.x;
    const int s0 = blockIdx.x * 4;
    int bb[4], nn[4];
    #pragma unroll
    for (int g = 0; g < 4; g++){
        int s = s0 + g;
        bb[g] = s / KKEEP;
        nn[g] = g_idx[bb[g]*KKEEP + (s % KKEEP)];
    }
    {
        const float4* zsrc = (const float4*)(g_zbuf + (size_t)s0*TT*CC);
        float4* zd = (float4*)sz;
        for (int i = tid; i < 4*TT*CC/4; i += 256) zd[i] = zsrc[i];
    }
    __syncthreads();

    // rmsnorm (norm2) over 64 rows
    const int wid = tid >> 5, lane = tid & 31;
    for (int r = wid; r < 64; r += 8){
        float* row = sz + r*CC;
        float v0 = row[lane], v1 = row[lane+32], v2 = row[lane+64], v3 = row[lane+96];
        float ss = v0*v0 + v1*v1 + v2*v2 + v3*v3;
        ss += __shfl_xor_sync(0xffffffffu, ss, 16);
        ss += __shfl_xor_sync(0xffffffffu, ss, 8);
        ss += __shfl_xor_sync(0xffffffffu, ss, 4);
        ss += __shfl_xor_sync(0xffffffffu, ss, 2);
        ss += __shfl_xor_sync(0xffffffffu, ss, 1);
        float sc = rsqrtf(ss*(1.f/CC) + 1e-5f);
        row[lane]    = v0*sc*norm2_w[lane];
        row[lane+32] = v1*sc*norm2_w[lane+32];
        row[lane+64] = v2*sc*norm2_w[lane+64];
        row[lane+96] = v3*sc*norm2_w[lane+96];
    }
    __syncthreads();

    const int cq = tid & 31;      // c0 = 4*cq, 128 cols
    const int tg = tid >> 5;      // rows tg*8 .. tg*8+7

    // w1 GEMM + exact GELU (coalesced wT LDG, broadcast act)
    {
        const float4* wT = (const float4*)g_w1T;            // [k][32 quads]
        const float4* ax = (const float4*)(sz + tg*8*CC);   // row i at + i*32
        float acc[4][8];
        const float4 bias = ((const float4*)b1)[cq];
        #pragma unroll
        for (int i = 0; i < 8; i++){ acc[0][i]=bias.x; acc[1][i]=bias.y; acc[2][i]=bias.z; acc[3][i]=bias.w; }
        for (int qq = 0; qq < 32; qq++){
            float4 act[8];
            #pragma unroll
            for (int i = 0; i < 8; i++) act[i] = ax[i*32 + qq];
            float4 w;
            w = __ldg(wT + (qq*4+0)*32 + cq);
            #pragma unroll
            for (int i = 0; i < 8; i++){ QFMA(acc, i, act[i].x, w) }
            w = __ldg(wT + (qq*4+1)*32 + cq);
            #pragma unroll
            for (int i = 0; i < 8; i++){ QFMA(acc, i, act[i].y, w) }
            w = __ldg(wT + (qq*4+2)*32 + cq);
            #pragma unroll
            for (int i = 0; i < 8; i++){ QFMA(acc, i, act[i].z, w) }
            w = __ldg(wT + (qq*4+3)*32 + cq);
            #pragma unroll
            for (int i = 0; i < 8; i++){ QFMA(acc, i, act[i].w, w) }
        }
        #pragma unroll
        for (int i = 0; i < 8; i++){
            float4 v;
            v.x = 0.5f*acc[0][i]*(1.f + erff(acc[0][i]*0.70710678118654752f));
            v.y = 0.5f*acc[1][i]*(1.f + erff(acc[1][i]*0.70710678118654752f));
            v.z = 0.5f*acc[2][i]*(1.f + erff(acc[2][i]*0.70710678118654752f));
            v.w = 0.5f*acc[3][i]*(1.f + erff(acc[3][i]*0.70710678118654752f));
            *(float4*)(sh1 + (tg*8+i)*CC + 4*cq) = v;
        }
    }
    __syncthreads();

    // w2 GEMM + residual scatter
    {
        const float4* wT = (const float4*)g_w2T;
        const float4* ax = (const float4*)(sh1 + tg*8*CC);
        float acc[4][8];
        const float4 bias = ((const float4*)b2)[cq];
        #pragma unroll
        for (int i = 0; i < 8; i++){ acc[0][i]=bias.x; acc[1][i]=bias.y; acc[2][i]=bias.z; acc[3][i]=bias.w; }
        for (int qq = 0; qq < 32; qq++){
            float4 act[8];
            #pragma unroll
            for (int i = 0; i < 8; i++) act[i] = ax[i*32 + qq];
            float4 w;
            w = __ldg(wT + (qq*4+0)*32 + cq);
            #pragma unroll
            for (int i = 0; i < 8; i++){ QFMA(acc, i, act[i].x, w) }
            w = __ldg(wT + (qq*4+1)*32 + cq);
            #pragma unroll
            for (int i = 0; i < 8; i++){ QFMA(acc, i, act[i].y, w) }
            w = __ldg(wT + (qq*4+2)*32 + cq);
            #pragma unroll
            for (int i = 0; i < 8; i++){ QFMA(acc, i, act[i].z, w) }
            w = __ldg(wT + (qq*4+3)*32 + cq);
            #pragma unroll
            for (int i = 0; i < 8; i++){ QFMA(acc, i, act[i].w, w) }
        }
        #pragma unroll
        for (int i = 0; i < 8; i++){
            int r = tg*8 + i;
            int g = r >> 4, t = r & 15;
            const size_t baseb = (size_t)bb[g]*TT*CC*HW + nn[g];
            #pragma unroll
            for (int jj = 0; jj < 4; jj++){
                size_t pos = baseb + (size_t)(t*CC + 4*cq + jj)*HW;
                out[pos] = x[pos] + acc[jj][i];
            }
        }
    }
}

// ---------------------------------------------------------------- launch
extern "C" void kernel_launch(void* const* d_in, const int* in_sizes, int n_in,
                              void* d_out, int out_size){
    const float* x    = (const float*)d_in[0];
    const float* n1w  = (const float*)d_in[1];
    const float* n2w  = (const float*)d_in[2];
    const float* inw  = (const float*)d_in[3];
    const float* cw   = (const float*)d_in[4];
    const float* cb   = (const float*)d_in[5];
    const float* xpw  = (const float*)d_in[6];
    const float* dtw  = (const float*)d_in[7];
    const float* dtb  = (const float*)d_in[8];
    const float* alog = (const float*)d_in[9];
    const float* dp   = (const float*)d_in[10];
    const float* ow   = (const float*)d_in[11];
    const float* w1   = (const float*)d_in[12];
    const float* b1   = (const float*)d_in[13];
    const float* w2   = (const float*)d_in[14];
    const float* b2   = (const float*)d_in[15];
    float* out = (float*)d_out;

    cudaFuncSetAttribute(k_mamba, cudaFuncAttributeMaxDynamicSharedMemorySize, SMEM_C_FLOATS*4);
    cudaFuncSetAttribute(k_mix,   cudaFuncAttributeMaxDynamicSharedMemorySize, SMEM_D_FLOATS*4);

    const int n4 = out_size / 4;
    k_wt<<<576, 256>>>(inw, xpw, ow, w1, w2);
    k_copy<<<(n4 + 255)/256, 256>>>((const float4*)x, (float4*)out, n4);
    k_energy<<<(BATCH*NPIX + 255)/256, 256>>>(x);
    k_select<<<BATCH, 768>>>();
    k_mamba<<<NSEQ, 256, SMEM_C_FLOATS*4>>>(x, n1w, cw, cb, dtw, dtb, alog, dp);
    k_mix<<<NSEQ/4, 256, SMEM_D_FLOATS*4>>>(x, n2w, b1, b2, out);
}

// round 7
// speedup vs baseline: 2.0155x; 1.3380x over previous
#include <cuda_runtime.h>
#include <math.h>

#define BATCH 2
#define TT 16
#define CC 128
#define HW 2304
#define NPIX 2304
#define DI 256
#define DS 16
#define KKEEP 1152
#define NSEQ (BATCH*KKEEP)

// scratch (static device globals; no allocations allowed)
__device__ float g_energy[BATCH*NPIX];
__device__ float g_part[BATCH*TT*NPIX];
__device__ int   g_keep[BATCH*NPIX];
__device__ int   g_idx[BATCH*KKEEP];
__device__ float g_zbuf[(size_t)NSEQ*TT*CC];
// transposed weights [k][j]
__device__ float g_inwT[128*512];
__device__ float g_xpwT[256*64];     // padded 40 -> 64 cols (zeros)
__device__ float g_owT[256*128];
__device__ float g_w1T[128*128];
__device__ float g_w2T[128*128];

// ---------------------------------------------------------------- weight transpose (tiny)
__global__ void k_wt(const float* __restrict__ in_w, const float* __restrict__ xp_w,
                     const float* __restrict__ out_w, const float* __restrict__ w1,
                     const float* __restrict__ w2){
    int id = blockIdx.x*256 + threadIdx.x;
    if (id < 65536){ int k=id>>9, j=id&511; g_inwT[id] = in_w[j*128+k]; return; }
    id -= 65536;
    if (id < 16384){ int k=id>>6, j=id&63; g_xpwT[id] = (j<40) ? xp_w[j*256+k] : 0.f; return; }
    id -= 16384;
    if (id < 32768){ int k=id>>7, j=id&127; g_owT[id] = out_w[j*256+k]; return; }
    id -= 32768;
    if (id < 16384){ int k=id>>7, j=id&127; g_w1T[id] = w1[j*128+k]; return; }
    id -= 16384;
    if (id < 16384){ int k=id>>7, j=id&127; g_w2T[id] = w2[j*128+k]; }
}

// ---------------------------------------------------------------- copy base
__global__ void k_copy(const float4* __restrict__ src, float4* __restrict__ dst, int n4){
    int i = blockIdx.x*blockDim.x + threadIdx.x;
    if (i < n4) dst[i] = src[i];
}

// ---------------------------------------------------------------- energy phase 1: per (b,t,n) sqrt of channel sumsq
__global__ void k_energy1(const float* __restrict__ x){
    int id = blockIdx.x*256 + threadIdx.x;
    if (id >= BATCH*TT*NPIX) return;
    int n = id % NPIX, bt = id / NPIX;
    const float* xt = x + (size_t)bt*CC*HW + n;
    float ss = 0.f;
    #pragma unroll 8
    for (int c = 0; c < CC; c++){
        float v = xt[(size_t)c*HW];
        ss += v*v;
    }
    g_part[id] = sqrtf(ss);
}

// ---------------------------------------------------------------- energy phase 2: mean over t
__global__ void k_energy2(){
    int id = blockIdx.x*256 + threadIdx.x;
    if (id >= BATCH*NPIX) return;
    int b = id / NPIX, n = id % NPIX;
    float e = 0.f;
    #pragma unroll
    for (int t = 0; t < TT; t++) e += g_part[(b*TT + t)*NPIX + n];
    g_energy[id] = e * (1.f/TT);
}

// ---------------------------------------------------------------- rank (stable: ties broken by index)
__global__ void k_rank(){
    __shared__ float se[NPIX];
    const int b = blockIdx.x / 9, chunk = blockIdx.x % 9;
    const int tid = threadIdx.x;
    for (int i = tid; i < NPIX; i += 256) se[i] = g_energy[b*NPIX + i];
    __syncthreads();
    const int n0 = chunk*256 + tid;
    const float e0 = se[n0];
    int r = 0;
    #pragma unroll 4
    for (int m = 0; m < NPIX; m++){
        float em = se[m];
        r += (em > e0) || (em == e0 && m < n0);
    }
    g_keep[b*NPIX + n0] = (r < KKEEP);
}

// ---------------------------------------------------------------- compact kept indices (sorted ascending)
__global__ void k_compact(){
    __shared__ int scnt[768];
    const int b = blockIdx.x, tid = threadIdx.x;
    const int n0 = tid*3;
    int k0 = g_keep[b*NPIX + n0], k1 = g_keep[b*NPIX + n0+1], k2 = g_keep[b*NPIX + n0+2];
    int cnt = k0 + k1 + k2;
    scnt[tid] = cnt;
    __syncthreads();
    for (int off = 1; off < 768; off <<= 1){
        int add = (tid >= off) ? scnt[tid-off] : 0;
        __syncthreads();
        scnt[tid] += add;
        __syncthreads();
    }
    int pos = scnt[tid] - cnt;
    if (k0) g_idx[b*KKEEP + pos++] = n0;
    if (k1) g_idx[b*KKEEP + pos++] = n0+1;
    if (k2) g_idx[b*KKEEP + pos++] = n0+2;
}

// FMA of scalar s against a j-quad w into 4 accumulators
#define QFMA(ACC, I, S, W) \
    ACC[0][I] += (S)*(W).x; ACC[1][I] += (S)*(W).y; ACC[2][I] += (S)*(W).z; ACC[3][I] += (S)*(W).w;

// ---------------------------------------------------------------- fused mamba per sequence
// smem floats: sx 2048 | sxi 4096 | szg 4096 | sdt 128 | sB 256 | sC 256 | red 4096 = 14976 (59904 B)
#define SMEM_C_FLOATS 14976
__global__ void __launch_bounds__(256, 3)
k_mamba(const float* __restrict__ x,
        const float* __restrict__ norm1_w,
        const float* __restrict__ conv_w,
        const float* __restrict__ conv_b,
        const float* __restrict__ dt_w,
        const float* __restrict__ dt_b,
        const float* __restrict__ A_log,
        const float* __restrict__ Dp){
    extern __shared__ float sm[];
    float* sx  = sm;             // [16][128]
    float* sxi = sm + 2048;      // [16][256] xi -> xc
    float* szg = sm + 6144;      // [16][256] z-gate -> y_act
    float* sdt = sm + 10240;     // [16][8]
    float* sB  = sm + 10368;     // [16][16]
    float* sC  = sm + 10624;     // [16][16]
    float* red = sm + 10880;     // [2][2048] k-split partials

    const int tid = threadIdx.x;
    const int seq = blockIdx.x;
    const int b = seq / KKEEP;
    const int n = g_idx[b*KKEEP + (seq % KKEEP)];

    // gather input rows
    const float* xb = x + (size_t)b*TT*CC*HW + n;
    for (int i = tid; i < TT*CC; i += 256){
        sx[i] = xb[(size_t)i * HW];
    }
    __syncthreads();

    // rmsnorm (norm1)
    const int wid = tid >> 5, lane = tid & 31;
    for (int r = wid; r < TT; r += 8){
        float* row = sx + r*CC;
        float v0 = row[lane], v1 = row[lane+32], v2 = row[lane+64], v3 = row[lane+96];
        float ss = v0*v0 + v1*v1 + v2*v2 + v3*v3;
        ss += __shfl_xor_sync(0xffffffffu, ss, 16);
        ss += __shfl_xor_sync(0xffffffffu, ss, 8);
        ss += __shfl_xor_sync(0xffffffffu, ss, 4);
        ss += __shfl_xor_sync(0xffffffffu, ss, 2);
        ss += __shfl_xor_sync(0xffffffffu, ss, 1);
        float sc = rsqrtf(ss*(1.f/CC) + 1e-5f);
        row[lane]    = v0*sc*norm1_w[lane];
        row[lane+32] = v1*sc*norm1_w[lane+32];
        row[lane+64] = v2*sc*norm1_w[lane+64];
        row[lane+96] = v3*sc*norm1_w[lane+96];
    }
    __syncthreads();

    // in_proj: [16,128] @ wT[128][512]. Thread: j-quad (jq=tid&127), 8 t (tg=tid>>7).
    {
        const int jq = tid & 127, tg = tid >> 7;
        const float4* wT = (const float4*)g_inwT;          // [k][128 quads]
        const float4* ax = (const float4*)(sx + tg*8*CC);  // row i at + i*32
        float acc[4][8];
        #pragma unroll
        for (int j = 0; j < 4; j++)
            #pragma unroll
            for (int i = 0; i < 8; i++) acc[j][i] = 0.f;
        for (int qq = 0; qq < 32; qq++){
            float4 act[8];
            #pragma unroll
            for (int i = 0; i < 8; i++) act[i] = ax[i*32 + qq];
            float4 w;
            w = __ldg(wT + (qq*4+0)*128 + jq);
            #pragma unroll
            for (int i = 0; i < 8; i++){ QFMA(acc, i, act[i].x, w) }
            w = __ldg(wT + (qq*4+1)*128 + jq);
            #pragma unroll
            for (int i = 0; i < 8; i++){ QFMA(acc, i, act[i].y, w) }
            w = __ldg(wT + (qq*4+2)*128 + jq);
            #pragma unroll
            for (int i = 0; i < 8; i++){ QFMA(acc, i, act[i].z, w) }
            w = __ldg(wT + (qq*4+3)*128 + jq);
            #pragma unroll
            for (int i = 0; i < 8; i++){ QFMA(acc, i, act[i].w, w) }
        }
        float* dst = (jq < 64) ? (sxi + 4*jq) : (szg + 4*jq - 256);
        #pragma unroll
        for (int i = 0; i < 8; i++){
            *(float4*)(dst + (tg*8+i)*DI) = make_float4(acc[0][i], acc[1][i], acc[2][i], acc[3][i]);
        }
    }
    __syncthreads();

    // causal depthwise conv (k=4) + SiLU, per channel
    {
        const int d = tid;
        const float w0 = conv_w[d*4], w1 = conv_w[d*4+1], w2 = conv_w[d*4+2], w3 = conv_w[d*4+3];
        const float cb = conv_b[d];
        float xv[TT+3];
        xv[0] = xv[1] = xv[2] = 0.f;
        #pragma unroll
        for (int t = 0; t < TT; t++) xv[t+3] = sxi[t*DI + d];
        #pragma unroll
        for (int t = 0; t < TT; t++){
            float a = cb + w0*xv[t] + w1*xv[t+1] + w2*xv[t+2] + w3*xv[t+3];
            sxi[t*DI + d] = a / (1.f + __expf(-a));
        }
    }
    __syncthreads();

    // x_proj: [16,256] @ wT[256][64pad]. K-split 2 x 128k; thread: jq(16) x tgrp(8 of 2t) x kg(2).
    {
        const int jq = tid & 15;
        const int tgrp = (tid >> 4) & 7;
        const int kg = tid >> 7;
        const float4* wT = (const float4*)g_xpwT;             // [k][16 quads]
        const float4* ax = (const float4*)(sxi + tgrp*2*DI);  // row i at + i*64
        float acc[4][2];
        #pragma unroll
        for (int j = 0; j < 4; j++){ acc[j][0] = 0.f; acc[j][1] = 0.f; }
        for (int qq = 0; qq < 32; qq++){
            const int q0 = kg*32 + qq;
            float4 act[2];
            act[0] = ax[q0]; act[1] = ax[64 + q0];
            float4 w;
            w = __ldg(wT + (q0*4+0)*16 + jq);
            QFMA(acc, 0, act[0].x, w)  QFMA(acc, 1, act[1].x, w)
            w = __ldg(wT + (q0*4+1)*16 + jq);
            QFMA(acc, 0, act[0].y, w)  QFMA(acc, 1, act[1].y, w)
            w = __ldg(wT + (q0*4+2)*16 + jq);
            QFMA(acc, 0, act[0].z, w)  QFMA(acc, 1, act[1].z, w)
            w = __ldg(wT + (q0*4+3)*16 + jq);
            QFMA(acc, 0, act[0].w, w)  QFMA(acc, 1, act[1].w, w)
        }
        #pragma unroll
        for (int i = 0; i < 2; i++){
            *(float4*)(red + kg*1024 + (tgrp*2+i)*64 + 4*jq) =
                make_float4(acc[0][i], acc[1][i], acc[2][i], acc[3][i]);
        }
    }
    __syncthreads();
    // reduce 2 partials -> route to sdt/sB/sC (1024 floats = 256 f4, 1 per thread)
    {
        const float4* r4 = (const float4*)red;
        float4 s0 = r4[tid], s1 = r4[256+tid];
        float v[4] = { s0.x+s1.x, s0.y+s1.y, s0.z+s1.z, s0.w+s1.w };
        #pragma unroll
        for (int c = 0; c < 4; c++){
            int idx = tid*4 + c;
            int j = idx & 63, t = idx >> 6;
            if (j < 8)       sdt[t*8 + j] = v[c];
            else if (j < 24) sB[t*16 + (j-8)] = v[c];
            else if (j < 40) sC[t*16 + (j-24)] = v[c];
        }
    }
    __syncthreads();

    // dt_proj + softplus + selective scan + gate (thread d owns channel d)
    {
        const int d = tid;
        float wdt[8];
        #pragma unroll
        for (int r = 0; r < 8; r++) wdt[r] = dt_w[d*8 + r];
        const float bdt = dt_b[d];
        float Ar[DS];
        #pragma unroll
        for (int s = 0; s < DS; s++) Ar[s] = -__expf(A_log[d*DS + s]);
        const float Dd = Dp[d];
        float h[DS];
        #pragma unroll
        for (int s = 0; s < DS; s++) h[s] = 0.f;
        for (int t = 0; t < TT; t++){
            float dtr = bdt;
            #pragma unroll
            for (int r = 0; r < 8; r++) dtr += sdt[t*8 + r]*wdt[r];
            float dtv = (dtr > 20.f) ? dtr : log1pf(__expf(dtr));
            float xcv = sxi[t*DI + d];
            float coef = dtv * xcv;
            float y = 0.f;
            #pragma unroll
            for (int s = 0; s < DS; s++){
                float dA = __expf(dtv * Ar[s]);
                h[s] = dA*h[s] + coef*sB[t*16 + s];
                y += h[s]*sC[t*16 + s];
            }
            float zg = szg[t*DI + d];
            szg[t*DI + d] = (y + xcv*Dd) * (zg / (1.f + __expf(-zg)));
        }
    }
    __syncthreads();

    // out_proj: [16,256] @ wT[256][128]. K-split 2 x 128k; thread: jq(32) x tgrp(4 of 4t) x kg(2).
    {
        const int jq = tid & 31;
        const int tgrp = (tid >> 5) & 3;
        const int kg = tid >> 7;
        const float4* wT = (const float4*)g_owT;              // [k][32 quads]
        const float4* ay = (const float4*)(szg + tgrp*4*DI);  // row i at + i*64
        float acc[4][4];
        #pragma unroll
        for (int j = 0; j < 4; j++)
            #pragma unroll
            for (int i = 0; i < 4; i++) acc[j][i] = 0.f;
        for (int qq = 0; qq < 32; qq++){
            const int q0 = kg*32 + qq;
            float4 act[4];
            #pragma unroll
            for (int i = 0; i < 4; i++) act[i] = ay[i*64 + q0];
            float4 w;
            w = __ldg(wT + (q0*4+0)*32 + jq);
            #pragma unroll
            for (int i = 0; i < 4; i++){ QFMA(acc, i, act[i].x, w) }
            w = __ldg(wT + (q0*4+1)*32 + jq);
            #pragma unroll
            for (int i = 0; i < 4; i++){ QFMA(acc, i, act[i].y, w) }
            w = __ldg(wT + (q0*4+2)*32 + jq);
            #pragma unroll
            for (int i = 0; i < 4; i++){ QFMA(acc, i, act[i].z, w) }
            w = __ldg(wT + (q0*4+3)*32 + jq);
            #pragma unroll
            for (int i = 0; i < 4; i++){ QFMA(acc, i, act[i].w, w) }
        }
        #pragma unroll
        for (int i = 0; i < 4; i++){
            *(float4*)(red + kg*2048 + (tgrp*4+i)*128 + 4*jq) =
                make_float4(acc[0][i], acc[1][i], acc[2][i], acc[3][i]);
        }
    }
    __syncthreads();
    // reduce 2 partials, write zbuf (coalesced): 2048 floats = 512 f4, 2 per thread
    {
        const float4* r4 = (const float4*)red;
        float4* zb = (float4*)(g_zbuf + (size_t)seq*TT*CC);
        #pragma unroll
        for (int p = 0; p < 2; p++){
            int o = tid + p*256;
            float4 s0 = r4[o], s1 = r4[512+o];
            zb[o] = make_float4(s0.x+s1.x, s0.y+s1.y, s0.z+s1.z, s0.w+s1.w);
        }
    }
}

// ---------------------------------------------------------------- mix MLP + scatter (4 sequences per block)
// smem floats: sz 8192 | sh1 8192 = 16384 (65536 B)
#define SMEM_D_FLOATS 16384
__global__ void __launch_bounds__(256, 3)
k_mix(const float* __restrict__ x,
      const float* __restrict__ norm2_w,
      const float* __restrict__ b1, const float* __restrict__ b2,
      float* __restrict__ out){
    extern __shared__ float sm[];
    float* sz  = sm;            // [64][128]
    float* sh1 = sm + 8192;     // [64][128]

    const int tid = threadIdx.x;
    const int s0 = blockIdx.x * 4;
    int bb[4], nn[4];
    #pragma unroll
    for (int g = 0; g < 4; g++){
        int s = s0 + g;
        bb[g] = s / KKEEP;
        nn[g] = g_idx[bb[g]*KKEEP + (s % KKEEP)];
    }
    {
        const float4* zsrc = (const float4*)(g_zbuf + (size_t)s0*TT*CC);
        float4* zd = (float4*)sz;
        for (int i = tid; i < 4*TT*CC/4; i += 256) zd[i] = zsrc[i];
    }
    __syncthreads();

    // rmsnorm (norm2) over 64 rows
    const int wid = tid >> 5, lane = tid & 31;
    for (int r = wid; r < 64; r += 8){
        float* row = sz + r*CC;
        float v0 = row[lane], v1 = row[lane+32], v2 = row[lane+64], v3 = row[lane+96];
        float ss = v0*v0 + v1*v1 + v2*v2 + v3*v3;
        ss += __shfl_xor_sync(0xffffffffu, ss, 16);
        ss += __shfl_xor_sync(0xffffffffu, ss, 8);
        ss += __shfl_xor_sync(0xffffffffu, ss, 4);
        ss += __shfl_xor_sync(0xffffffffu, ss, 2);
        ss += __shfl_xor_sync(0xffffffffu, ss, 1);
        float sc = rsqrtf(ss*(1.f/CC) + 1e-5f);
        row[lane]    = v0*sc*norm2_w[lane];
        row[lane+32] = v1*sc*norm2_w[lane+32];
        row[lane+64] = v2*sc*norm2_w[lane+64];
        row[lane+96] = v3*sc*norm2_w[lane+96];
    }
    __syncthreads();

    const int cq = tid & 31;      // c0 = 4*cq, 128 cols
    const int tg = tid >> 5;      // rows tg*8 .. tg*8+7

    // w1 GEMM + exact GELU (coalesced wT LDG, broadcast act)
    {
        const float4* wT = (const float4*)g_w1T;            // [k][32 quads]
        const float4* ax = (const float4*)(sz + tg*8*CC);   // row i at + i*32
        float acc[4][8];
        const float4 bias = ((const float4*)b1)[cq];
        #pragma unroll
        for (int i = 0; i < 8; i++){ acc[0][i]=bias.x; acc[1][i]=bias.y; acc[2][i]=bias.z; acc[3][i]=bias.w; }
        for (int qq = 0; qq < 32; qq++){
            float4 act[8];
            #pragma unroll
            for (int i = 0; i < 8; i++) act[i] = ax[i*32 + qq];
            float4 w;
            w = __ldg(wT + (qq*4+0)*32 + cq);
            #pragma unroll
            for (int i = 0; i < 8; i++){ QFMA(acc, i, act[i].x, w) }
            w = __ldg(wT + (qq*4+1)*32 + cq);
            #pragma unroll
            for (int i = 0; i < 8; i++){ QFMA(acc, i, act[i].y, w) }
            w = __ldg(wT + (qq*4+2)*32 + cq);
            #pragma unroll
            for (int i = 0; i < 8; i++){ QFMA(acc, i, act[i].z, w) }
            w = __ldg(wT + (qq*4+3)*32 + cq);
            #pragma unroll
            for (int i = 0; i < 8; i++){ QFMA(acc, i, act[i].w, w) }
        }
        #pragma unroll
        for (int i = 0; i < 8; i++){
            float4 v;
            v.x = 0.5f*acc[0][i]*(1.f + erff(acc[0][i]*0.70710678118654752f));
            v.y = 0.5f*acc[1][i]*(1.f + erff(acc[1][i]*0.70710678118654752f));
            v.z = 0.5f*acc[2][i]*(1.f + erff(acc[2][i]*0.70710678118654752f));
            v.w = 0.5f*acc[3][i]*(1.f + erff(acc[3][i]*0.70710678118654752f));
            *(float4*)(sh1 + (tg*8+i)*CC + 4*cq) = v;
        }
    }
    __syncthreads();

    // w2 GEMM + residual scatter
    {
        const float4* wT = (const float4*)g_w2T;
        const float4* ax = (const float4*)(sh1 + tg*8*CC);
        float acc[4][8];
        const float4 bias = ((const float4*)b2)[cq];
        #pragma unroll
        for (int i = 0; i < 8; i++){ acc[0][i]=bias.x; acc[1][i]=bias.y; acc[2][i]=bias.z; acc[3][i]=bias.w; }
        for (int qq = 0; qq < 32; qq++){
            float4 act[8];
            #pragma unroll
            for (int i = 0; i < 8; i++) act[i] = ax[i*32 + qq];
            float4 w;
            w = __ldg(wT + (qq*4+0)*32 + cq);
            #pragma unroll
            for (int i = 0; i < 8; i++){ QFMA(acc, i, act[i].x, w) }
            w = __ldg(wT + (qq*4+1)*32 + cq);
            #pragma unroll
            for (int i = 0; i < 8; i++){ QFMA(acc, i, act[i].y, w) }
            w = __ldg(wT + (qq*4+2)*32 + cq);
            #pragma unroll
            for (int i = 0; i < 8; i++){ QFMA(acc, i, act[i].z, w) }
            w = __ldg(wT + (qq*4+3)*32 + cq);
            #pragma unroll
            for (int i = 0; i < 8; i++){ QFMA(acc, i, act[i].w, w) }
        }
        #pragma unroll
        for (int i = 0; i < 8; i++){
            int r = tg*8 + i;
            int g = r >> 4, t = r & 15;
            const size_t baseb = (size_t)bb[g]*TT*CC*HW + nn[g];
            #pragma unroll
            for (int jj = 0; jj < 4; jj++){
                size_t pos = baseb + (size_t)(t*CC + 4*cq + jj)*HW;
                out[pos] = x[pos] + acc[jj][i];
            }
        }
    }
}

// ---------------------------------------------------------------- launch
extern "C" void kernel_launch(void* const* d_in, const int* in_sizes, int n_in,
                              void* d_out, int out_size){
    const float* x    = (const float*)d_in[0];
    const float* n1w  = (const float*)d_in[1];
    const float* n2w  = (const float*)d_in[2];
    const float* inw  = (const float*)d_in[3];
    const float* cw   = (const float*)d_in[4];
    const float* cb   = (const float*)d_in[5];
    const float* xpw  = (const float*)d_in[6];
    const float* dtw  = (const float*)d_in[7];
    const float* dtb  = (const float*)d_in[8];
    const float* alog = (const float*)d_in[9];
    const float* dp   = (const float*)d_in[10];
    const float* ow   = (const float*)d_in[11];
    const float* w1   = (const float*)d_in[12];
    const float* b1   = (const float*)d_in[13];
    const float* w2   = (const float*)d_in[14];
    const float* b2   = (const float*)d_in[15];
    float* out = (float*)d_out;

    cudaFuncSetAttribute(k_mamba, cudaFuncAttributeMaxDynamicSharedMemorySize, SMEM_C_FLOATS*4);
    cudaFuncSetAttribute(k_mix,   cudaFuncAttributeMaxDynamicSharedMemorySize, SMEM_D_FLOATS*4);

    const int n4 = out_size / 4;
    k_wt<<<576, 256>>>(inw, xpw, ow, w1, w2);
    k_copy<<<(n4 + 255)/256, 256>>>((const float4*)x, (float4*)out, n4);
    k_energy1<<<(BATCH*TT*NPIX + 255)/256, 256>>>(x);
    k_energy2<<<(BATCH*NPIX + 255)/256, 256>>>();
    k_rank<<<BATCH*9, 256>>>();
    k_compact<<<BATCH, 768>>>();
    k_mamba<<<NSEQ, 256, SMEM_C_FLOATS*4>>>(x, n1w, cw, cb, dtw, dtb, alog, dp);
    k_mix<<<NSEQ/4, 256, SMEM_D_FLOATS*4>>>(x, n2w, b1, b2, out);
}